// round 2
// baseline (speedup 1.0000x reference)
#include <cuda_runtime.h>

#define HH 1024
#define WW 1024
#define NPIX (HH * WW)
#define NB 8

// Ping-pong scratch: [ping][x_or_y][image*NPIX]
__device__ float  g_buf[2][2][NB * NPIX];
__device__ float  g_part[5][256];
__device__ double g_term[NB];

// ---------------------------------------------------------------------------
// Kernel 1: channel sum  S[b] = x[b,0]+x[b,1]+x[b,2]  (and same for y)
// ---------------------------------------------------------------------------
__global__ void sum_ch_kernel(const float4* __restrict__ x,
                              const float4* __restrict__ y) {
    const int n4 = NPIX / 4;
    int i = blockIdx.x * blockDim.x + threadIdx.x;
    if (i >= NB * n4) return;
    int img = i / n4;
    int p   = i - img * n4;

    const float4* xs = x + (size_t)img * 3 * n4;
    float4 a = xs[p], b = xs[p + n4], c = xs[p + 2 * n4];
    ((float4*)g_buf[0][0])[i] =
        make_float4(a.x + b.x + c.x, a.y + b.y + c.y,
                    a.z + b.z + c.z, a.w + b.w + c.w);

    const float4* ys = y + (size_t)img * 3 * n4;
    a = ys[p]; b = ys[p + n4]; c = ys[p + 2 * n4];
    ((float4*)g_buf[0][1])[i] =
        make_float4(a.x + b.x + c.x, a.y + b.y + c.y,
                    a.z + b.z + c.z, a.w + b.w + c.w);
}

// ---------------------------------------------------------------------------
// Kernel 2: 3x3 zero-padded conv, smem-tiled. Tile = 128x8 outputs/block.
// blockIdx.z enumerates (x planes for img t..7) then (y planes for img t..7).
// ---------------------------------------------------------------------------
__global__ void conv_kernel(int srcp, int t) {
    const int nimg = NB - t;
    int z  = blockIdx.z;
    int xy = (z >= nimg) ? 1 : 0;
    int img = t + z - xy * nimg;
    const float* __restrict__ src = g_buf[srcp][xy]     + (size_t)img * NPIX;
    float*       __restrict__ dst = g_buf[srcp ^ 1][xy] + (size_t)img * NPIX;

    __shared__ float s[10][132];
    const int x0 = blockIdx.x * 128;
    const int y0 = blockIdx.y * 8;
    const int tid = threadIdx.y * 32 + threadIdx.x;

    // Load (128+2) x (8+2) halo tile with zero fill at image boundary
    for (int i = tid; i < 10 * 130; i += 256) {
        int r = i / 130, c = i - r * 130;
        int gy = y0 - 1 + r, gx = x0 - 1 + c;
        float v = 0.0f;
        if ((unsigned)gy < HH && (unsigned)gx < WW) v = src[gy * WW + gx];
        s[r][c] = v;
    }
    __syncthreads();

    const float KA = 0.03797616f;   // corners
    const float KB = 0.044863533f;  // edges
    const float KC = 0.053f;        // center
    const int ty = threadIdx.y;
    const int cx = threadIdx.x * 4 + 1;

    float o[4];
#pragma unroll
    for (int j = 0; j < 4; j++) {
        int cc = cx + j;
        o[j] = KA * (s[ty][cc - 1] + s[ty][cc + 1] + s[ty + 2][cc - 1] + s[ty + 2][cc + 1])
             + KB * (s[ty][cc] + s[ty + 2][cc] + s[ty + 1][cc - 1] + s[ty + 1][cc + 1])
             + KC * s[ty + 1][cc];
    }
    *(float4*)(dst + (size_t)(y0 + ty) * WW + x0 + threadIdx.x * 4) =
        make_float4(o[0], o[1], o[2], o[3]);
}

// ---------------------------------------------------------------------------
// Kernel 3: 5-moment reduction over image t (u = conv^(t+1) Sx, v = same for y)
// ---------------------------------------------------------------------------
__inline__ __device__ float warpSumF(float v) {
#pragma unroll
    for (int o = 16; o; o >>= 1) v += __shfl_down_sync(0xffffffffu, v, o);
    return v;
}

__global__ void stats_kernel(int ping, int t) {
    const float4* __restrict__ u = (const float4*)(g_buf[ping][0] + (size_t)t * NPIX);
    const float4* __restrict__ v = (const float4*)(g_buf[ping][1] + (size_t)t * NPIX);
    float su = 0, su2 = 0, sv = 0, sv2 = 0, suv = 0;
    const int n4 = NPIX / 4;
    for (int i = blockIdx.x * blockDim.x + threadIdx.x; i < n4;
         i += gridDim.x * blockDim.x) {
        float4 a = u[i], b = v[i];
        su  += a.x + a.y + a.z + a.w;
        su2 += a.x * a.x + a.y * a.y + a.z * a.z + a.w * a.w;
        sv  += b.x + b.y + b.z + b.w;
        sv2 += b.x * b.x + b.y * b.y + b.z * b.z + b.w * b.w;
        suv += a.x * b.x + a.y * b.y + a.z * b.z + a.w * b.w;
    }
    su = warpSumF(su); su2 = warpSumF(su2); sv = warpSumF(sv);
    sv2 = warpSumF(sv2); suv = warpSumF(suv);

    __shared__ float sm[5][8];
    int lane = threadIdx.x & 31, w = threadIdx.x >> 5;
    if (lane == 0) {
        sm[0][w] = su; sm[1][w] = su2; sm[2][w] = sv;
        sm[3][w] = sv2; sm[4][w] = suv;
    }
    __syncthreads();
    if (threadIdx.x == 0) {
#pragma unroll
        for (int k = 0; k < 5; k++) {
            float r = 0.0f;
#pragma unroll
            for (int q = 0; q < 8; q++) r += sm[k][q];
            g_part[k][blockIdx.x] = r;
        }
    }
}

// ---------------------------------------------------------------------------
// Kernel 4: finalize one SSIM term (double precision)
// ---------------------------------------------------------------------------
__inline__ __device__ double warpSumD(double v) {
#pragma unroll
    for (int o = 16; o; o >>= 1) v += __shfl_down_sync(0xffffffffu, v, o);
    return v;
}

__global__ void finalize_kernel(int t) {
    double a0 = (double)g_part[0][threadIdx.x];
    double a1 = (double)g_part[1][threadIdx.x];
    double a2 = (double)g_part[2][threadIdx.x];
    double a3 = (double)g_part[3][threadIdx.x];
    double a4 = (double)g_part[4][threadIdx.x];
    a0 = warpSumD(a0); a1 = warpSumD(a1); a2 = warpSumD(a2);
    a3 = warpSumD(a3); a4 = warpSumD(a4);

    __shared__ double sm[5][8];
    int lane = threadIdx.x & 31, w = threadIdx.x >> 5;
    if (lane == 0) {
        sm[0][w] = a0; sm[1][w] = a1; sm[2][w] = a2;
        sm[3][w] = a3; sm[4][w] = a4;
    }
    __syncthreads();
    if (threadIdx.x == 0) {
        double SU = 0, SU2 = 0, SV = 0, SV2 = 0, SUV = 0;
#pragma unroll
        for (int q = 0; q < 8; q++) {
            SU += sm[0][q]; SU2 += sm[1][q]; SV += sm[2][q];
            SV2 += sm[3][q]; SUV += sm[4][q];
        }
        double sc = 1.0;
        for (int i = 0; i < t; i++) sc *= 3.0;  // 3^t channel-mixing gain
        const double N = (double)NPIX;
        const double C1 = 6.5025;    // (0.01*255)^2
        const double C2 = 58.5225;   // (0.03*255)^2
        double mu = sc * SU / N;
        double mv = sc * SV / N;
        double varu = sc * sc * (SU2 - SU * SU / N) / (N - 1.0);
        double varv = sc * sc * (SV2 - SV * SV / N) / (N - 1.0);
        double cov  = sc * sc * (SUV - SU * SV / N) / (N - 1.0);
        g_term[t] = ((2.0 * mu * mv + C1) * (2.0 * cov + C2)) /
                    ((mu * mu + mv * mv + C1) * (varu * varu + varv * varv + C2));
    }
}

__global__ void sum8_kernel(float* __restrict__ out) {
    double s = 0.0;
#pragma unroll
    for (int i = 0; i < NB; i++) s += g_term[i];
    out[0] = (float)s;
}

// ---------------------------------------------------------------------------
extern "C" void kernel_launch(void* const* d_in, const int* in_sizes, int n_in,
                              void* d_out, int out_size) {
    const float4* x = (const float4*)d_in[0];
    const float4* y = (const float4*)d_in[1];
    float* out = (float*)d_out;

    // 1) channel sums into ping 0
    sum_ch_kernel<<<(NB * NPIX / 4 + 255) / 256, 256>>>(x, y);

    // 2) 8 iterations: conv images [t,8) for both inputs, then stats on image t
    for (int t = 0; t < NB; t++) {
        dim3 grid(WW / 128, HH / 8, 2 * (NB - t));
        conv_kernel<<<grid, dim3(32, 8)>>>(t & 1, t);
        stats_kernel<<<256, 256>>>((t & 1) ^ 1, t);
        finalize_kernel<<<1, 256>>>(t);
    }

    // 3) sum the 8 terms
    sum8_kernel<<<1, 1>>>(out);
}